// round 17
// baseline (speedup 1.0000x reference)
#include <cuda_runtime.h>
#include <cstdint>

// TTStack: out[b, (a c d), (i j l)] = sum_{k1,k2} c0[idx,a,i,k1] * c1[idx,k1,c,j,k2] * c2[idx,k2,d,l]
// c0 [1000,8,8,16], c1 [1000,16,8,8,16], c2 [1000,16,8,8], indices [512] i32 -> out [512,512,512] f32.
//
// R16 design: two-phase per (b,a) block.
//   Phase A: thread (c,i,j) computes t[row=tid][k2=16] in registers (as before),
//            then parks t in smem (overlapping the dead c1 region).
//   Phase B: register-tiled GEMM t[512x16] x c2[16x64]: thread owns 8 t-rows x 8 (l) cols
//            for one d, two passes over j-halves (acc fits 64-reg budget).
//            smem loads drop ~2.6x vs the 1-row-x-64-col scheme (L1 was 87% bound).

#define THREADS 512
#define C1_PAD 20   // c1 k2-row padded 16 -> 20 floats: conflict-free LDS.128 across j
#define C2_PAD 12   // c2 l-row padded 8 -> 12 floats: lane-distinct d loads tile all banks

static constexpr int SM_C1  = 16 * 8 * 8 * C1_PAD;   // 20480 floats (reused as t_s in phase B)
static constexpr int SM_C2  = 16 * 8 * C2_PAD;       // 1536 floats
static constexpr int SM_C0  = 8 * 16;                // 128 floats
static constexpr size_t SMEM_BYTES = (size_t)(SM_C1 + SM_C2 + SM_C0) * sizeof(float);

typedef unsigned long long ull;

__device__ __forceinline__ ull ffma2(ull a, ull b, ull c) {
    ull d;
    asm("fma.rn.f32x2 %0, %1, %2, %3;" : "=l"(d) : "l"(a), "l"(b), "l"(c));
    return d;
}
__device__ __forceinline__ ull pack2(float x, float y) {
    ull r;
    asm("mov.b64 %0, {%1, %2};" : "=l"(r) : "f"(x), "f"(y));
    return r;
}
__device__ __forceinline__ float2 unpack2(ull v) {
    float2 r;
    asm("mov.b64 {%0, %1}, %2;" : "=f"(r.x), "=f"(r.y) : "l"(v));
    return r;
}

__global__ __launch_bounds__(THREADS, 2)
void tt_stack_kernel(const float* __restrict__ core0,
                     const float* __restrict__ core1,
                     const float* __restrict__ core2,
                     const int*   __restrict__ indices,
                     float*       __restrict__ out)
{
    extern __shared__ float smem[];
    float* sC1 = smem;                   // phase A: [k1][c][j][k2 pad 20]; phase B: t_s
    float* sC2 = smem + SM_C1;           // [k2][d][l pad 12]
    float* sC0 = smem + SM_C1 + SM_C2;   // [i][k1]

    const int b   = blockIdx.y;
    const int a   = blockIdx.x;
    const int tid = threadIdx.x;
    const int idx = indices[b];

    // ---- stage cores into smem ----
    {
        const float4* g1 = reinterpret_cast<const float4*>(core1 + (size_t)idx * 16384);
        float4* s1 = reinterpret_cast<float4*>(sC1);
        #pragma unroll
        for (int u = tid; u < 4096; u += THREADS) {
            int row = u >> 2;                    // (k1*8+c)*8+j
            int q   = u & 3;
            s1[row * (C1_PAD / 4) + q] = g1[u];
        }
        if (tid < 256) {
            // c2 gmem [k2][d][l]: tid -> k2=tid>>4, d=(tid>>1)&7, half=tid&1
            float4 g = reinterpret_cast<const float4*>(core2 + (size_t)idx * 1024)[tid];
            int k2 = tid >> 4, d = (tid >> 1) & 7, h = tid & 1;
            reinterpret_cast<float4*>(sC2 + k2 * (8 * C2_PAD) + d * C2_PAD + h * 4)[0] = g;
        }
        if (tid < 32) {
            reinterpret_cast<float4*>(sC0)[tid] =
                reinterpret_cast<const float4*>(core0 + (size_t)idx * 1024 + a * 128)[tid];
        }
    }
    __syncthreads();

    // ---- phase A: t[k2] = sum_k1 c0[a,i,k1] * c1[k1,c,j,k2]; row == tid ----
    const int cA = tid >> 6;
    const int iA = (tid >> 3) & 7;
    const int jA = tid & 7;

    ull tacc[8];
    #pragma unroll
    for (int q = 0; q < 8; q++) tacc[q] = 0ull;

    {
        const float* c0row = sC0 + iA * 16;
        const int rowbase = (cA * 8 + jA) * C1_PAD;
        #pragma unroll
        for (int k1 = 0; k1 < 16; k1++) {
            float av = c0row[k1];
            ull avv = pack2(av, av);
            const ulonglong2* p =
                reinterpret_cast<const ulonglong2*>(sC1 + k1 * (64 * C1_PAD) + rowbase);
            #pragma unroll
            for (int q = 0; q < 4; q++) {
                ulonglong2 v = p[q];
                tacc[2 * q]     = ffma2(avv, v.x, tacc[2 * q]);
                tacc[2 * q + 1] = ffma2(avv, v.y, tacc[2 * q + 1]);
            }
        }
    }
    __syncthreads();   // all sC1 reads done; safe to overwrite with t_s

    // ---- park t: t_s[kp][row][2] as one u64 per (kp,row); row == tid ----
    {
        ull* tS = reinterpret_cast<ull*>(smem);
        #pragma unroll
        for (int kp = 0; kp < 8; kp++)
            tS[kp * 512 + tid] = tacc[kp];      // {t[2kp], t[2kp+1]}
    }
    __syncthreads();

    // ---- phase B: out tile 8 rows (j) x 8 cols (l), fixed (c,i,d); 2 passes over j ----
    const int rg = tid >> 3;        // 0..63 = (c,i)
    const int d  = tid & 7;
    const int cB = rg >> 3;
    const int iB = rg & 7;

    const float4* t4 = reinterpret_cast<const float4*>(smem);   // t_s as float4: 2 rows x 2 k2
    float* ob = out + ((size_t)b * 512 + (size_t)((a * 8 + cB) * 8 + d)) * 512
                    + (size_t)(iB * 64);

    #pragma unroll
    for (int jh = 0; jh < 2; jh++) {
        ull acc[16];
        #pragma unroll
        for (int q = 0; q < 16; q++) acc[q] = 0ull;

        const int rbase = rg * 8 + jh * 4;
        #pragma unroll
        for (int kp = 0; kp < 8; kp++) {
            // t for rows rbase..rbase+3, k2 = 2kp, 2kp+1
            float4 ta = t4[kp * 256 + (rbase >> 1)];        // {r0:ka, r0:kb, r1:ka, r1:kb}
            float4 tb = t4[kp * 256 + (rbase >> 1) + 1];    // {r2:ka, r2:kb, r3:ka, r3:kb}

            // k2 = 2kp
            {
                const ulonglong2* pc2 =
                    reinterpret_cast<const ulonglong2*>(sC2 + (2 * kp) * (8 * C2_PAD) + d * C2_PAD);
                ulonglong2 va = pc2[0];   // l0..3
                ulonglong2 vb = pc2[1];   // l4..7
                ull t0 = pack2(ta.x, ta.x), t1 = pack2(ta.z, ta.z);
                ull t2 = pack2(tb.x, tb.x), t3 = pack2(tb.z, tb.z);
                acc[0]  = ffma2(t0, va.x, acc[0]);  acc[1]  = ffma2(t0, va.y, acc[1]);
                acc[2]  = ffma2(t0, vb.x, acc[2]);  acc[3]  = ffma2(t0, vb.y, acc[3]);
                acc[4]  = ffma2(t1, va.x, acc[4]);  acc[5]  = ffma2(t1, va.y, acc[5]);
                acc[6]  = ffma2(t1, vb.x, acc[6]);  acc[7]  = ffma2(t1, vb.y, acc[7]);
                acc[8]  = ffma2(t2, va.x, acc[8]);  acc[9]  = ffma2(t2, va.y, acc[9]);
                acc[10] = ffma2(t2, vb.x, acc[10]); acc[11] = ffma2(t2, vb.y, acc[11]);
                acc[12] = ffma2(t3, va.x, acc[12]); acc[13] = ffma2(t3, va.y, acc[13]);
                acc[14] = ffma2(t3, vb.x, acc[14]); acc[15] = ffma2(t3, vb.y, acc[15]);
            }
            // k2 = 2kp + 1
            {
                const ulonglong2* pc2 =
                    reinterpret_cast<const ulonglong2*>(sC2 + (2 * kp + 1) * (8 * C2_PAD) + d * C2_PAD);
                ulonglong2 va = pc2[0];
                ulonglong2 vb = pc2[1];
                ull t0 = pack2(ta.y, ta.y), t1 = pack2(ta.w, ta.w);
                ull t2 = pack2(tb.y, tb.y), t3 = pack2(tb.w, tb.w);
                acc[0]  = ffma2(t0, va.x, acc[0]);  acc[1]  = ffma2(t0, va.y, acc[1]);
                acc[2]  = ffma2(t0, vb.x, acc[2]);  acc[3]  = ffma2(t0, vb.y, acc[3]);
                acc[4]  = ffma2(t1, va.x, acc[4]);  acc[5]  = ffma2(t1, va.y, acc[5]);
                acc[6]  = ffma2(t1, vb.x, acc[6]);  acc[7]  = ffma2(t1, vb.y, acc[7]);
                acc[8]  = ffma2(t2, va.x, acc[8]);  acc[9]  = ffma2(t2, va.y, acc[9]);
                acc[10] = ffma2(t2, vb.x, acc[10]); acc[11] = ffma2(t2, vb.y, acc[11]);
                acc[12] = ffma2(t3, va.x, acc[12]); acc[13] = ffma2(t3, va.y, acc[13]);
                acc[14] = ffma2(t3, vb.x, acc[14]); acc[15] = ffma2(t3, vb.y, acc[15]);
            }
        }

        // stores: rows j = jh*4+jr  -> cols iB*64 + j*8 + l  (128B contiguous per lane/pass)
        #pragma unroll
        for (int jr = 0; jr < 4; jr++) {
            float2 p0 = unpack2(acc[jr * 4 + 0]);
            float2 p1 = unpack2(acc[jr * 4 + 1]);
            float2 p2 = unpack2(acc[jr * 4 + 2]);
            float2 p3 = unpack2(acc[jr * 4 + 3]);
            float* row = ob + (size_t)(jh * 4 + jr) * 8;
            reinterpret_cast<float4*>(row)[0] = make_float4(p0.x, p0.y, p1.x, p1.y);
            reinterpret_cast<float4*>(row)[1] = make_float4(p2.x, p2.y, p3.x, p3.y);
        }
    }
}

extern "C" void kernel_launch(void* const* d_in, const int* in_sizes, int n_in,
                              void* d_out, int out_size)
{
    const float* core0   = (const float*)d_in[0];
    const float* core1   = (const float*)d_in[1];
    const float* core2   = (const float*)d_in[2];
    const int*   indices = (const int*)d_in[3];
    const int B = in_sizes[3];   // 512

    cudaFuncSetAttribute(tt_stack_kernel,
                         cudaFuncAttributeMaxDynamicSharedMemorySize,
                         (int)SMEM_BYTES);

    dim3 grid(8, B, 1);          // (a, b)
    tt_stack_kernel<<<grid, THREADS, SMEM_BYTES>>>(core0, core1, core2, indices,
                                                   (float*)d_out);
}